// round 5
// baseline (speedup 1.0000x reference)
#include <cuda_runtime.h>
#include <cuda_bf16.h>

// BackwardRPM: 16384 independent 200-step solves.
//   per step: h = tanh(u@W1 + b1) (64,), grad6 = C@h + d - s, u = clip(u - 0.01*grad6)
// with A = R[:, :6]^T R (6x40), C = A W2^T (6x64), d = A@b2, s = A@spec.
//
// R4: occupancy push. cp (grad weights) moved to shared memory (-48 regs),
// u kept permanently packed (-6), v-chain split 2-way (shorter dep path),
// launch_bounds(128,4) -> 16 warps/SM. Butterfly reduction (redux.f32 does
// not exist on sm_103a).

#define STEPS 200
#define LR 0.01f
#define BATCH 16384
#define HID 64
#define PROJ 8
#define NSPEC 40

typedef unsigned long long u64x;

__device__ float g_A[6 * NSPEC];   // A = R6^T R
__device__ float g_C[6 * HID];     // C = A W2^T
__device__ float g_d[6];           // d = A b2

__global__ void precompute_kernel(const float* __restrict__ W2,
                                  const float* __restrict__ b2,
                                  const float* __restrict__ R) {
    __shared__ float sA[6 * NSPEC];
    int tid = threadIdx.x;

    for (int t = tid; t < 6 * NSPEC; t += blockDim.x) {
        int i = t / NSPEC, k = t % NSPEC;
        float acc = 0.0f;
#pragma unroll
        for (int p = 0; p < PROJ; ++p)
            acc = fmaf(R[p * NSPEC + i], R[p * NSPEC + k], acc);
        sA[t] = acc;
        g_A[t] = acc;
    }
    __syncthreads();

    for (int t = tid; t < 6 * HID; t += blockDim.x) {
        int i = t / HID, j = t % HID;
        float acc = 0.0f;
#pragma unroll
        for (int k = 0; k < NSPEC; ++k)
            acc = fmaf(sA[i * NSPEC + k], W2[j * NSPEC + k], acc);
        g_C[t] = acc;
    }

    if (tid < 6) {
        float acc = 0.0f;
#pragma unroll
        for (int k = 0; k < NSPEC; ++k)
            acc = fmaf(sA[tid * NSPEC + k], b2[k], acc);
        g_d[tid] = acc;
    }
}

// ---- f32x2 helpers ----
__device__ __forceinline__ u64x pack2(float lo, float hi) {
    u64x r; asm("mov.b64 %0, {%1, %2};" : "=l"(r) : "f"(lo), "f"(hi)); return r;
}
__device__ __forceinline__ void unpack2(u64x v, float& lo, float& hi) {
    asm("mov.b64 {%0, %1}, %2;" : "=f"(lo), "=f"(hi) : "l"(v));
}
__device__ __forceinline__ u64x fma2(u64x a, u64x b, u64x c) {
    u64x d; asm("fma.rn.f32x2 %0, %1, %2, %3;" : "=l"(d) : "l"(a), "l"(b), "l"(c)); return d;
}
__device__ __forceinline__ u64x mul2(u64x a, u64x b) {
    u64x d; asm("mul.rn.f32x2 %0, %1, %2;" : "=l"(d) : "l"(a), "l"(b)); return d;
}
__device__ __forceinline__ u64x add2(u64x a, u64x b) {
    u64x d; asm("add.rn.f32x2 %0, %1, %2;" : "=l"(d) : "l"(a), "l"(b)); return d;
}
__device__ __forceinline__ float tanh_fast(float x) {
    float y; asm("tanh.approx.f32 %0, %1;" : "=f"(y) : "f"(x)); return y;
}

__global__ void __launch_bounds__(128, 4)
solve_kernel(const float* __restrict__ spectrum,
             const float* __restrict__ W1,
             const float* __restrict__ b1,
             float* __restrict__ out) {
    // cp in shared: s_cp[(i*4+p)*8 + sub] = (C[i][sub+16p], C[i][sub+16p+8])
    __shared__ u64x s_cp[6 * 4 * 8];

    const int tid = threadIdx.x;
    const int gtid = blockIdx.x * blockDim.x + tid;
    const int sample = gtid >> 3;       // 8 lanes per sample
    const int sub = gtid & 7;           // hidden-dim slice

    // Fill s_cp cooperatively (192 entries, 128 threads).
    for (int t = tid; t < 6 * 4 * 8; t += 128) {
        int i = t >> 5;
        int rem = t & 31;
        int p = rem >> 3;
        int s = rem & 7;
        s_cp[t] = pack2(g_C[i * HID + s + 16 * p],
                        g_C[i * HID + s + 16 * p + 8]);
    }
    __syncthreads();

    if (sample >= BATCH) return;

    // w1 pairs + b1 pairs in registers: pair p covers (sub+16p, sub+16p+8).
    u64x w1p[6][4];
    u64x b1p[4];
#pragma unroll
    for (int p = 0; p < 4; ++p) {
        int j0 = sub + 16 * p;
        int j1 = j0 + 8;
        b1p[p] = pack2(__ldg(&b1[j0]), __ldg(&b1[j1]));
#pragma unroll
        for (int i = 0; i < 6; ++i)
            w1p[i][p] = pack2(__ldg(&W1[i * HID + j0]), __ldg(&W1[i * HID + j1]));
    }

    // base[i] = d[i] - (A @ spec)[i]
    const float* sp = spectrum + sample * NSPEC;
    float base[6];
#pragma unroll
    for (int i = 0; i < 6; ++i) {
        float acc = 0.0f;
#pragma unroll
        for (int k = 0; k < NSPEC; ++k)
            acc = fmaf(g_A[i * NSPEC + k], __ldg(&sp[k]), acc);
        base[i] = g_d[i] - acc;
    }

    // u permanently packed as (u, u).
    u64x uq[6];
#pragma unroll
    for (int i = 0; i < 6; ++i) uq[i] = pack2(0.5f, 0.5f);

#pragma unroll 1
    for (int t = 0; t < STEPS; ++t) {
        u64x g2[6];
#pragma unroll
        for (int i = 0; i < 6; ++i) g2[i] = 0ull;

#pragma unroll
        for (int p = 0; p < 4; ++p) {
            // v = b1 + u@W1slice, split into two 3-deep chains.
            u64x c0 = fma2(uq[0], w1p[0][p], b1p[p]);
            c0 = fma2(uq[1], w1p[1][p], c0);
            c0 = fma2(uq[2], w1p[2][p], c0);
            u64x c1 = mul2(uq[3], w1p[3][p]);
            c1 = fma2(uq[4], w1p[4][p], c1);
            c1 = fma2(uq[5], w1p[5][p], c1);
            u64x v = add2(c0, c1);

            float v0, v1;
            unpack2(v, v0, v1);
            u64x hp = pack2(tanh_fast(v0), tanh_fast(v1));
#pragma unroll
            for (int i = 0; i < 6; ++i)
                g2[i] = fma2(hp, s_cp[(i * 4 + p) * 8 + sub], g2[i]);
        }

        // collapse pair halves -> 6 scalars, pack into 3 f32x2.
        float gr[6];
#pragma unroll
        for (int i = 0; i < 6; ++i) {
            float a, b;
            unpack2(g2[i], a, b);
            gr[i] = a + b;
        }
        u64x r0 = pack2(gr[0], gr[1]);
        u64x r1 = pack2(gr[2], gr[3]);
        u64x r2 = pack2(gr[4], gr[5]);
#pragma unroll
        for (int d = 1; d < 8; d <<= 1) {
            r0 = add2(r0, __shfl_xor_sync(0xffffffffu, r0, d));
            r1 = add2(r1, __shfl_xor_sync(0xffffffffu, r1, d));
            r2 = add2(r2, __shfl_xor_sync(0xffffffffu, r2, d));
        }
        unpack2(r0, gr[0], gr[1]);
        unpack2(r1, gr[2], gr[3]);
        unpack2(r2, gr[4], gr[5]);

#pragma unroll
        for (int i = 0; i < 6; ++i) {
            float g = gr[i] + base[i];
            float ulo, uhi;
            unpack2(uq[i], ulo, uhi);
            (void)uhi;
            float un = fmaf(-LR, g, ulo);
            un = fminf(1.0f, fmaxf(0.0f, un));
            uq[i] = pack2(un, un);
        }
    }

    if (sub == 0) {
        float r[6], hi;
#pragma unroll
        for (int i = 0; i < 6; ++i) { unpack2(uq[i], r[i], hi); (void)hi; }
#pragma unroll
        for (int i = 0; i < 6; ++i)
            out[sample * 6 + i] = r[i];
    }
}

extern "C" void kernel_launch(void* const* d_in, const int* in_sizes, int n_in,
                              void* d_out, int out_size) {
    // metadata order: spectrum, W1, b1, W2, b2, R
    const float* spectrum = (const float*)d_in[0];
    const float* W1 = (const float*)d_in[1];
    const float* b1 = (const float*)d_in[2];
    const float* W2 = (const float*)d_in[3];
    const float* b2 = (const float*)d_in[4];
    const float* R  = (const float*)d_in[5];
    float* out = (float*)d_out;

    precompute_kernel<<<1, 256>>>(W2, b2, R);

    const int threads = 128;
    const int total = BATCH * 8;
    solve_kernel<<<total / threads, threads>>>(spectrum, W1, b1, out);
}

// round 6
// speedup vs baseline: 1.1488x; 1.1488x over previous
#include <cuda_runtime.h>
#include <cuda_bf16.h>

// BackwardRPM: 16384 independent 200-step solves.
//   per step: h = tanh(u@W1 + b1) (64,), grad6 = C@h + d - s, u = clip(u - 0.01*grad6)
// with A = R[:, :6]^T R (6x40), C = A W2^T (6x64), d = A@b2, s = A@spec.
//
// R5: back to all-register weights (R2 layout: 8 lanes/sample, f32x2 pairs),
// now with TWO samples per thread. Weight registers are shared between the two
// samples; two independent dependency chains per warp hide the per-step
// latency (MUFU + 3-round butterfly) that limited R2 to fma=61%.

#define STEPS 200
#define LR 0.01f
#define BATCH 16384
#define HID 64
#define PROJ 8
#define NSPEC 40

typedef unsigned long long u64x;

__device__ float g_A[6 * NSPEC];   // A = R6^T R
__device__ float g_C[6 * HID];     // C = A W2^T
__device__ float g_d[6];           // d = A b2

__global__ void precompute_kernel(const float* __restrict__ W2,
                                  const float* __restrict__ b2,
                                  const float* __restrict__ R) {
    __shared__ float sA[6 * NSPEC];
    int tid = threadIdx.x;

    for (int t = tid; t < 6 * NSPEC; t += blockDim.x) {
        int i = t / NSPEC, k = t % NSPEC;
        float acc = 0.0f;
#pragma unroll
        for (int p = 0; p < PROJ; ++p)
            acc = fmaf(R[p * NSPEC + i], R[p * NSPEC + k], acc);
        sA[t] = acc;
        g_A[t] = acc;
    }
    __syncthreads();

    for (int t = tid; t < 6 * HID; t += blockDim.x) {
        int i = t / HID, j = t % HID;
        float acc = 0.0f;
#pragma unroll
        for (int k = 0; k < NSPEC; ++k)
            acc = fmaf(sA[i * NSPEC + k], W2[j * NSPEC + k], acc);
        g_C[t] = acc;
    }

    if (tid < 6) {
        float acc = 0.0f;
#pragma unroll
        for (int k = 0; k < NSPEC; ++k)
            acc = fmaf(sA[tid * NSPEC + k], b2[k], acc);
        g_d[tid] = acc;
    }
}

// ---- f32x2 helpers ----
__device__ __forceinline__ u64x pack2(float lo, float hi) {
    u64x r; asm("mov.b64 %0, {%1, %2};" : "=l"(r) : "f"(lo), "f"(hi)); return r;
}
__device__ __forceinline__ void unpack2(u64x v, float& lo, float& hi) {
    asm("mov.b64 {%0, %1}, %2;" : "=f"(lo), "=f"(hi) : "l"(v));
}
__device__ __forceinline__ u64x fma2(u64x a, u64x b, u64x c) {
    u64x d; asm("fma.rn.f32x2 %0, %1, %2, %3;" : "=l"(d) : "l"(a), "l"(b), "l"(c)); return d;
}
__device__ __forceinline__ u64x add2(u64x a, u64x b) {
    u64x d; asm("add.rn.f32x2 %0, %1, %2;" : "=l"(d) : "l"(a), "l"(b)); return d;
}
__device__ __forceinline__ float tanh_fast(float x) {
    float y; asm("tanh.approx.f32 %0, %1;" : "=f"(y) : "f"(x)); return y;
}

__global__ void __launch_bounds__(128, 2)
solve_kernel(const float* __restrict__ spectrum,
             const float* __restrict__ W1,
             const float* __restrict__ b1,
             float* __restrict__ out) {
    const int gtid = blockIdx.x * blockDim.x + threadIdx.x;
    const int sampleA = gtid >> 3;          // 8 lanes per sample
    const int sampleB = sampleA + (BATCH / 2);
    const int sub = gtid & 7;               // hidden-dim slice
    if (sampleA >= BATCH / 2) return;

    // Weight pairs in registers: pair p covers j0 = sub+16p, j1 = j0+8.
    // Shared between both samples.
    u64x w1p[6][4];
    u64x cp[6][4];
    u64x b1p[4];
#pragma unroll
    for (int p = 0; p < 4; ++p) {
        int j0 = sub + 16 * p;
        int j1 = j0 + 8;
        b1p[p] = pack2(__ldg(&b1[j0]), __ldg(&b1[j1]));
#pragma unroll
        for (int i = 0; i < 6; ++i) {
            w1p[i][p] = pack2(__ldg(&W1[i * HID + j0]), __ldg(&W1[i * HID + j1]));
            cp[i][p]  = pack2(g_C[i * HID + j0], g_C[i * HID + j1]);
        }
    }

    // base[i] = d[i] - (A @ spec)[i] for each sample
    const float* spA = spectrum + sampleA * NSPEC;
    const float* spB = spectrum + sampleB * NSPEC;
    float baseA[6], baseB[6];
#pragma unroll
    for (int i = 0; i < 6; ++i) {
        float accA = 0.0f, accB = 0.0f;
#pragma unroll
        for (int k = 0; k < NSPEC; ++k) {
            float a = g_A[i * NSPEC + k];
            accA = fmaf(a, __ldg(&spA[k]), accA);
            accB = fmaf(a, __ldg(&spB[k]), accB);
        }
        baseA[i] = g_d[i] - accA;
        baseB[i] = g_d[i] - accB;
    }

    // u state, permanently packed as (u, u).
    u64x uA[6], uB[6];
#pragma unroll
    for (int i = 0; i < 6; ++i) { uA[i] = pack2(0.5f, 0.5f); uB[i] = uA[i]; }

#pragma unroll 1
    for (int t = 0; t < STEPS; ++t) {
        u64x gA[6], gB[6];
#pragma unroll
        for (int i = 0; i < 6; ++i) { gA[i] = 0ull; gB[i] = 0ull; }

#pragma unroll
        for (int p = 0; p < 4; ++p) {
            // two independent v-chains (A and B) interleave in the scheduler
            u64x vA = b1p[p];
            u64x vB = b1p[p];
#pragma unroll
            for (int i = 0; i < 6; ++i) {
                vA = fma2(uA[i], w1p[i][p], vA);
                vB = fma2(uB[i], w1p[i][p], vB);
            }
            float a0, a1, c0, c1;
            unpack2(vA, a0, a1);
            unpack2(vB, c0, c1);
            u64x hA = pack2(tanh_fast(a0), tanh_fast(a1));
            u64x hB = pack2(tanh_fast(c0), tanh_fast(c1));
#pragma unroll
            for (int i = 0; i < 6; ++i) {
                gA[i] = fma2(hA, cp[i][p], gA[i]);
                gB[i] = fma2(hB, cp[i][p], gB[i]);
            }
        }

        // collapse pair halves -> scalars
        float grA[6], grB[6];
#pragma unroll
        for (int i = 0; i < 6; ++i) {
            float a, b;
            unpack2(gA[i], a, b); grA[i] = a + b;
            unpack2(gB[i], a, b); grB[i] = a + b;
        }

        // butterfly over the 8-lane group; A and B reductions overlap
        u64x rA0 = pack2(grA[0], grA[1]);
        u64x rA1 = pack2(grA[2], grA[3]);
        u64x rA2 = pack2(grA[4], grA[5]);
        u64x rB0 = pack2(grB[0], grB[1]);
        u64x rB1 = pack2(grB[2], grB[3]);
        u64x rB2 = pack2(grB[4], grB[5]);
#pragma unroll
        for (int d = 1; d < 8; d <<= 1) {
            rA0 = add2(rA0, __shfl_xor_sync(0xffffffffu, rA0, d));
            rB0 = add2(rB0, __shfl_xor_sync(0xffffffffu, rB0, d));
            rA1 = add2(rA1, __shfl_xor_sync(0xffffffffu, rA1, d));
            rB1 = add2(rB1, __shfl_xor_sync(0xffffffffu, rB1, d));
            rA2 = add2(rA2, __shfl_xor_sync(0xffffffffu, rA2, d));
            rB2 = add2(rB2, __shfl_xor_sync(0xffffffffu, rB2, d));
        }
        unpack2(rA0, grA[0], grA[1]);
        unpack2(rA1, grA[2], grA[3]);
        unpack2(rA2, grA[4], grA[5]);
        unpack2(rB0, grB[0], grB[1]);
        unpack2(rB1, grB[2], grB[3]);
        unpack2(rB2, grB[4], grB[5]);

#pragma unroll
        for (int i = 0; i < 6; ++i) {
            float lo, hi;
            float gAi = grA[i] + baseA[i];
            unpack2(uA[i], lo, hi); (void)hi;
            float unA = fminf(1.0f, fmaxf(0.0f, fmaf(-LR, gAi, lo)));
            uA[i] = pack2(unA, unA);

            float gBi = grB[i] + baseB[i];
            unpack2(uB[i], lo, hi); (void)hi;
            float unB = fminf(1.0f, fmaxf(0.0f, fmaf(-LR, gBi, lo)));
            uB[i] = pack2(unB, unB);
        }
    }

    if (sub == 0) {
        float r, hi;
#pragma unroll
        for (int i = 0; i < 6; ++i) {
            unpack2(uA[i], r, hi); (void)hi;
            out[sampleA * 6 + i] = r;
        }
#pragma unroll
        for (int i = 0; i < 6; ++i) {
            unpack2(uB[i], r, hi); (void)hi;
            out[sampleB * 6 + i] = r;
        }
    }
}

extern "C" void kernel_launch(void* const* d_in, const int* in_sizes, int n_in,
                              void* d_out, int out_size) {
    // metadata order: spectrum, W1, b1, W2, b2, R
    const float* spectrum = (const float*)d_in[0];
    const float* W1 = (const float*)d_in[1];
    const float* b1 = (const float*)d_in[2];
    const float* W2 = (const float*)d_in[3];
    const float* b2 = (const float*)d_in[4];
    const float* R  = (const float*)d_in[5];
    float* out = (float*)d_out;

    precompute_kernel<<<1, 256>>>(W2, b2, R);

    const int threads = 128;
    const int total = (BATCH / 2) * 8;   // 2 samples per thread
    solve_kernel<<<total / threads, threads>>>(spectrum, W1, b1, out);
}